// round 13
// baseline (speedup 1.0000x reference)
#include <cuda_runtime.h>
#include <cuda_fp16.h>
#include <cstdint>

// Problem constants
#define Hh 768
#define Lq 384
#define Bq 2
#define NROWS (Bq * Lq)           // 768 rows of (b, l)
#define M_PAIRS 73920             // 384*385/2
#define NXE (768 * 768)           // X elements
#define NWE (1536 * 768)          // W elements (as 1536 virtual K-major rows)
#define GEMM_CTAS 144
#define GEMM_THREADS 256
#define CVT_UNITS ((NXE + NWE) / 8)               // 221184 = 144*256*6

// Scratch
__device__ float g_A[NROWS * Hh];             // X @ W[:, :768]^T + bias
__device__ float g_Bv[NROWS * Hh];            // X @ W[:, 768:]^T
__device__ __align__(16) __half g_Xh[NXE];
__device__ __align__(16) __half g_Wh[NWE];

// Grid-barrier state: monotonic across graph replays (no reset needed).
__device__ unsigned g_arrive = 0;
__device__ unsigned g_release = 0;

__device__ __forceinline__ uint32_t smem_u32(const void* p) {
    uint32_t a;
    asm("{ .reg .u64 t; cvta.to.shared.u64 t, %1; cvt.u32.u64 %0, t; }" : "=r"(a) : "l"(p));
    return a;
}

// Pack 4 floats -> 4 fp16 (rn) in a uint2
__device__ __forceinline__ uint2 cvt4h(const float4 v) {
    __half2 p0 = __floats2half2_rn(v.x, v.y);
    __half2 p1 = __floats2half2_rn(v.z, v.w);
    uint2 r;
    r.x = *reinterpret_cast<uint32_t*>(&p0);
    r.y = *reinterpret_cast<uint32_t*>(&p1);
    return r;
}

// ---------------------------------------------------------------------------
// mma.sync primitives
// ---------------------------------------------------------------------------
__device__ __forceinline__ void ldsm4(uint32_t& r0, uint32_t& r1, uint32_t& r2,
                                      uint32_t& r3, uint32_t addr) {
    asm volatile("ldmatrix.sync.aligned.m8n8.x4.shared.b16 {%0,%1,%2,%3}, [%4];"
                 : "=r"(r0), "=r"(r1), "=r"(r2), "=r"(r3) : "r"(addr));
}
__device__ __forceinline__ void mma16816(float* d, const uint32_t* a, const uint32_t* b) {
    asm volatile(
        "mma.sync.aligned.m16n8k16.row.col.f32.f16.f16.f32 "
        "{%0,%1,%2,%3}, {%4,%5,%6,%7}, {%8,%9}, {%0,%1,%2,%3};"
        : "+f"(d[0]), "+f"(d[1]), "+f"(d[2]), "+f"(d[3])
        : "r"(a[0]), "r"(a[1]), "r"(a[2]), "r"(a[3]), "r"(b[0]), "r"(b[1]));
}
#define CPA16(dst, src) \
    asm volatile("cp.async.cg.shared.global [%0], [%1], 16;" :: "r"(dst), "l"(src))
#define CPA_COMMIT() asm volatile("cp.async.commit_group;" ::: "memory")
#define CPA_WAIT2()  asm volatile("cp.async.wait_group 2;" ::: "memory")

#define STAGE_B   15360                   // bytes per pipeline stage
#define SB_OFF    10240                   // B tile offset within a stage
#define GEMM_SMEM (4 * STAGE_B)           // 61440

// ---------------------------------------------------------------------------
// Kernel 1: fused convert + single-pass fp16 mma.sync GEMM.
// Phase A: 144 co-resident CTAs convert X and W (fp32 -> fp16, W re-packed
//          into 1536 K-major virtual rows), 6 x 8-elem units per thread.
// Phase B: monotonic-epoch grid barrier (all CTAs resident: 144 CTAs,
//          61KB smem -> <=3/SM needed on 148 SMs, so spin is deadlock-free).
// Phase C: GEMM D[m,n] = sum_k Xh[m,k]*Wh[n,k], CTA tile 128x64, 8 warps,
//          BK=32, 4-stage cp.async ring. Epilogue adds bias into g_A / g_Bv.
// ---------------------------------------------------------------------------
__global__ __launch_bounds__(GEMM_THREADS) void mma_gemm(const float* __restrict__ X,
                                                         const float* __restrict__ W,
                                                         const float* __restrict__ bias) {
    extern __shared__ char smem[];
    const uint32_t S = smem_u32(smem);

    const int tid = threadIdx.x;
    const int cta = blockIdx.y * gridDim.x + blockIdx.x;   // 0..143

    // ---- Phase A: conversion slice (6 units of 8 elems) ----
#pragma unroll
    for (int it = 0; it < 6; ++it) {
        const int u = cta * GEMM_THREADS + tid + it * (GEMM_CTAS * GEMM_THREADS);
        const int e = u * 8;
        float4 v0, v1;
        __half* dst;
        if (e < NXE) {
            v0 = *reinterpret_cast<const float4*>(X + e);
            v1 = *reinterpret_cast<const float4*>(X + e + 4);
            dst = g_Xh + e;
        } else {
            const int e2 = e - NXE;
            const int n = e2 / 768;
            const int k = e2 - n * 768;
            const int p = (n >= 768);
            const int h = n - p * 768;
            const float* src = W + (size_t)h * 1536 + p * 768 + k;
            v0 = *reinterpret_cast<const float4*>(src);
            v1 = *reinterpret_cast<const float4*>(src + 4);
            dst = g_Wh + e2;
        }
        const uint2 a = cvt4h(v0);
        const uint2 b = cvt4h(v1);
        *reinterpret_cast<uint4*>(dst) = make_uint4(a.x, a.y, b.x, b.y);
    }

    // ---- Phase B: grid barrier (monotonic epochs, replay-safe) ----
    __threadfence();                       // publish conversions
    __syncthreads();                       // all threads of CTA done
    if (tid == 0) {
        const unsigned my = atomicAdd(&g_arrive, 1u) + 1u;       // 1-based
        const unsigned epoch = (my + GEMM_CTAS - 1u) / GEMM_CTAS; // ceil
        if (my % GEMM_CTAS == 0u) atomicAdd(&g_release, 1u);      // last arriver
        while (true) {
            unsigned r;
            asm volatile("ld.acquire.gpu.u32 %0, [%1];" : "=r"(r) : "l"(&g_release));
            if (r >= epoch) break;
        }
    }
    __syncthreads();
    __threadfence();                       // acquire converted data

    // ---- Phase C: GEMM ----
    const int wid = tid >> 5, lane = tid & 31;
    const int wm = wid >> 1, wn = wid & 1;        // warp grid 4(m) x 2(n)
    const int col0 = blockIdx.x * 64;             // virtual-W-row tile (0..1535)
    const int row0 = blockIdx.y * 128;            // X-row tile (0..767)
    const int part = (col0 >= Hh);
    const int hb = col0 - part * Hh;

#define SA_ADDR(BUF, ROW, COLSH) \
    (S + (uint32_t)(BUF) * STAGE_B + (uint32_t)((ROW) * 80 + (COLSH) * 2))
#define SB_ADDR(BUF, ROW, COLSH) \
    (S + (uint32_t)(BUF) * STAGE_B + SB_OFF + (uint32_t)((ROW) * 80 + (COLSH) * 2))

    const int cr = tid >> 2;                      // 0..63
    const int ck = (tid & 3) * 8;                 // k offset in elems
    const size_t aBase0 = (size_t)(row0 + cr) * 768 + ck;
    const size_t aBase1 = (size_t)(row0 + cr + 64) * 768 + ck;
    const size_t bBase  = (size_t)(col0 + cr) * 768 + ck;

    const int aq = lane >> 3, al8 = lane & 7;
    const int a_row = wm * 32 + (aq & 1) * 8 + al8;
    const int a_col = (aq >> 1) * 8;
    const int b_row0 = wn * 32 + (aq >> 1) * 8 + al8;
    const int b_col = (aq & 1) * 8;

    float acc[2][4][4];
#pragma unroll
    for (int i = 0; i < 2; i++)
#pragma unroll
        for (int j = 0; j < 4; j++)
#pragma unroll
            for (int c = 0; c < 4; c++) acc[i][j][c] = 0.0f;

#define PREFETCH(BUF, K0)                                                     \
    do {                                                                      \
        CPA16(SA_ADDR(BUF, cr, ck),      g_Xh + aBase0 + (K0));               \
        CPA16(SA_ADDR(BUF, cr + 64, ck), g_Xh + aBase1 + (K0));               \
        CPA16(SB_ADDR(BUF, cr, ck),      g_Wh + bBase + (K0));                \
        CPA_COMMIT();                                                         \
    } while (0)

    PREFETCH(0, 0);
    PREFETCH(1, 32);
    PREFETCH(2, 64);

    for (int t = 0; t < 24; ++t) {
        const int buf = t & 3;
        CPA_WAIT2();
        __syncthreads();
        if (t + 3 < 24) PREFETCH((t + 3) & 3, (t + 3) * 32);

#pragma unroll
        for (int ksub = 0; ksub < 2; ++ksub) {
            const int kc = ksub * 16;
            uint32_t Af[2][4];
            uint32_t Bf[4][2];
#pragma unroll
            for (int fm = 0; fm < 2; fm++)
                ldsm4(Af[fm][0], Af[fm][1], Af[fm][2], Af[fm][3],
                      SA_ADDR(buf, a_row + fm * 16, kc + a_col));
#pragma unroll
            for (int fp = 0; fp < 2; fp++)
                ldsm4(Bf[fp * 2][0], Bf[fp * 2][1], Bf[fp * 2 + 1][0], Bf[fp * 2 + 1][1],
                      SB_ADDR(buf, b_row0 + fp * 16, kc + b_col));
#pragma unroll
            for (int fm = 0; fm < 2; fm++)
#pragma unroll
                for (int fn = 0; fn < 4; fn++)
                    mma16816(acc[fm][fn], Af[fm], Bf[fn]);
        }
    }

    // Epilogue: acc -> g_A (with bias) / g_Bv
    float* dst = part ? g_Bv : g_A;
    const int r_base = row0 + wm * 32 + (lane >> 2);
    const int c_base = hb + wn * 32 + (lane & 3) * 2;
#pragma unroll
    for (int fm = 0; fm < 2; fm++)
#pragma unroll
        for (int fn = 0; fn < 4; fn++) {
            const int cc = c_base + fn * 8;
            float2 b0 = make_float2(0.f, 0.f);
            if (!part) b0 = *reinterpret_cast<const float2*>(bias + cc);
#pragma unroll
            for (int hr = 0; hr < 2; hr++) {
                const int rr = r_base + fm * 16 + hr * 8;
                float2 v;
                v.x = acc[fm][fn][hr * 2 + 0] + b0.x;
                v.y = acc[fm][fn][hr * 2 + 1] + b0.y;
                *reinterpret_cast<float2*>(dst + (size_t)rr * Hh + cc) = v;
            }
        }
}

// ---------------------------------------------------------------------------
// Fast tanh: tanh(z) = 1 - 2/(exp(2z)+1).
// ---------------------------------------------------------------------------
__device__ __forceinline__ float fast_tanh(float z) {
    const float e = __expf(2.0f * z);
    return 1.0f - __fdividef(2.0f, e + 1.0f);
}

// ---------------------------------------------------------------------------
// Kernel 2 (at the HBM write floor — do not touch):
// out[b, m(i,j), h] = tanh(A[b,i,h] + Bv[b,j,h]) for j >= i.
// IT=4 x JT=8 tile, 192 threads, float4 per thread, ii-outer with bv cached.
// ---------------------------------------------------------------------------
__global__ __launch_bounds__(192) void pairs_kernel(float* __restrict__ out) {
    const int b  = blockIdx.z;
    const int i0 = blockIdx.y * 4;
    const int j0 = blockIdx.x * 8;
    if (j0 + 8 <= i0) return;

    const int t = threadIdx.x;
    const int h0 = t * 4;

    float4 a[4];
#pragma unroll
    for (int ii = 0; ii < 4; ii++)
        a[ii] = *reinterpret_cast<const float4*>(g_A + (size_t)(b * Lq + i0 + ii) * Hh + h0);

    float4 bv[8];
#pragma unroll
    for (int jj = 0; jj < 8; jj++)
        bv[jj] = *reinterpret_cast<const float4*>(g_Bv + (size_t)(b * Lq + j0 + jj) * Hh + h0);

#pragma unroll
    for (int ii = 0; ii < 4; ii++) {
        const int i = i0 + ii;
        const int rowbase = i * Lq - (i * (i - 1)) / 2 - i;
        float* obase = out + ((size_t)(b * M_PAIRS + rowbase + j0)) * Hh + h0;
#pragma unroll
        for (int jj = 0; jj < 8; jj++) {
            const int j = j0 + jj;
            if (j >= i) {
                float4 v;
                v.x = fast_tanh(a[ii].x + bv[jj].x);
                v.y = fast_tanh(a[ii].y + bv[jj].y);
                v.z = fast_tanh(a[ii].z + bv[jj].z);
                v.w = fast_tanh(a[ii].w + bv[jj].w);
                __stcs(reinterpret_cast<float4*>(obase + (size_t)jj * Hh), v);
            }
        }
    }
}

// ---------------------------------------------------------------------------
// Launch: seq_hiddens [2,384,768] f32, W [768,1536] f32, b [768] f32.
// Output [2, 73920, 768] f32.
// ---------------------------------------------------------------------------
extern "C" void kernel_launch(void* const* d_in, const int* in_sizes, int n_in,
                              void* d_out, int out_size) {
    const float* seq  = (const float*)d_in[0];
    const float* W    = (const float*)d_in[1];
    const float* bias = (const float*)d_in[2];
    float* out = (float*)d_out;

    cudaFuncSetAttribute(mma_gemm, cudaFuncAttributeMaxDynamicSharedMemorySize, GEMM_SMEM);

    dim3 g1(24, 6);       // (N/64 over 1536, M/128 over 768) = 144 CTAs, one wave
    mma_gemm<<<g1, GEMM_THREADS, GEMM_SMEM>>>(seq, W, bias);

    dim3 g2(48, 96, 2);   // (384/8 j-tiles, 384/4 i-tiles, batch)
    pairs_kernel<<<g2, 192>>>(out);
}

// round 14
// speedup vs baseline: 1.0108x; 1.0108x over previous
#include <cuda_runtime.h>
#include <cuda_fp16.h>
#include <cstdint>
#include <cmath>

// Problem constants
#define Hh 768
#define Lq 384
#define Bq 2
#define NROWS (Bq * Lq)           // 768 rows of (b, l)
#define M_PAIRS 73920             // 384*385/2
#define NXE (768 * 768)           // X elements
#define NWE (1536 * 768)          // W elements (as 1536 virtual K-major rows)
#define PAIR_TILES 2352           // valid (i0/4, j0/8) tiles per batch

// Scratch
__device__ float g_A[NROWS * Hh];             // X @ W[:, :768]^T + bias
__device__ float g_Bv[NROWS * Hh];            // X @ W[:, 768:]^T
__device__ __align__(16) __half g_Xh[NXE];
__device__ __align__(16) __half g_Wh[NWE];

__device__ __forceinline__ uint32_t smem_u32(const void* p) {
    uint32_t a;
    asm("{ .reg .u64 t; cvta.to.shared.u64 t, %1; cvt.u32.u64 %0, t; }" : "=r"(a) : "l"(p));
    return a;
}

// Pack 4 floats -> 4 fp16 (rn) in a uint2
__device__ __forceinline__ uint2 cvt4h(const float4 v) {
    __half2 p0 = __floats2half2_rn(v.x, v.y);
    __half2 p1 = __floats2half2_rn(v.z, v.w);
    uint2 r;
    r.x = *reinterpret_cast<uint32_t*>(&p0);
    r.y = *reinterpret_cast<uint32_t*>(&p1);
    return r;
}

// ---------------------------------------------------------------------------
// Kernel 0: fp32 -> fp16 convert, 8 elems/thread: 2x LDG.128 -> 1x STG.128.
// W re-packed into 1536 K-major virtual rows: row n = p*768+h holds
// W[h, p*768 + k], k in [0,768).
// ---------------------------------------------------------------------------
__global__ __launch_bounds__(256) void convert_kernel(const float* __restrict__ X,
                                                      const float* __restrict__ W) {
    const int e = (blockIdx.x * 256 + threadIdx.x) * 8;
    float4 v0, v1;
    __half* dst;
    if (e < NXE) {
        v0 = *reinterpret_cast<const float4*>(X + e);
        v1 = *reinterpret_cast<const float4*>(X + e + 4);
        dst = g_Xh + e;
    } else {
        const int e2 = e - NXE;
        const int n = e2 / 768;
        const int k = e2 - n * 768;
        const int p = (n >= 768);
        const int h = n - p * 768;
        const float* src = W + (size_t)h * 1536 + p * 768 + k;
        v0 = *reinterpret_cast<const float4*>(src);
        v1 = *reinterpret_cast<const float4*>(src + 4);
        dst = g_Wh + e2;
    }
    const uint2 a = cvt4h(v0);
    const uint2 b = cvt4h(v1);
    *reinterpret_cast<uint4*>(dst) = make_uint4(a.x, a.y, b.x, b.y);
}

// ---------------------------------------------------------------------------
// Kernel 1: single-pass fp16 mma.sync GEMM (fp32 accumulate), BK=32,
// 4-stage cp.async ring. D[m,n] = sum_k Xh[m,k] * Wh[n,k].
// CTA tile 128x64, 8 warps (4m x 2n). 61440 B dynamic smem. 144 CTAs.
// ---------------------------------------------------------------------------
__device__ __forceinline__ void ldsm4(uint32_t& r0, uint32_t& r1, uint32_t& r2,
                                      uint32_t& r3, uint32_t addr) {
    asm volatile("ldmatrix.sync.aligned.m8n8.x4.shared.b16 {%0,%1,%2,%3}, [%4];"
                 : "=r"(r0), "=r"(r1), "=r"(r2), "=r"(r3) : "r"(addr));
}
__device__ __forceinline__ void mma16816(float* d, const uint32_t* a, const uint32_t* b) {
    asm volatile(
        "mma.sync.aligned.m16n8k16.row.col.f32.f16.f16.f32 "
        "{%0,%1,%2,%3}, {%4,%5,%6,%7}, {%8,%9}, {%0,%1,%2,%3};"
        : "+f"(d[0]), "+f"(d[1]), "+f"(d[2]), "+f"(d[3])
        : "r"(a[0]), "r"(a[1]), "r"(a[2]), "r"(a[3]), "r"(b[0]), "r"(b[1]));
}
#define CPA16(dst, src) \
    asm volatile("cp.async.cg.shared.global [%0], [%1], 16;" :: "r"(dst), "l"(src))
#define CPA_COMMIT() asm volatile("cp.async.commit_group;" ::: "memory")
#define CPA_WAIT2()  asm volatile("cp.async.wait_group 2;" ::: "memory")

#define STAGE_B   15360                   // bytes per pipeline stage
#define SB_OFF    10240                   // B tile offset within a stage
#define GEMM_SMEM (4 * STAGE_B)           // 61440

__global__ __launch_bounds__(256) void mma_gemm(const float* __restrict__ bias) {
    extern __shared__ char smem[];
    const uint32_t S = smem_u32(smem);

    const int tid = threadIdx.x;
    const int wid = tid >> 5, lane = tid & 31;
    const int wm = wid >> 1, wn = wid & 1;        // warp grid 4(m) x 2(n)
    const int col0 = blockIdx.x * 64;             // virtual-W-row tile (0..1535)
    const int row0 = blockIdx.y * 128;            // X-row tile (0..767)
    const int part = (col0 >= Hh);
    const int hb = col0 - part * Hh;

#define SA_ADDR(BUF, ROW, COLSH) \
    (S + (uint32_t)(BUF) * STAGE_B + (uint32_t)((ROW) * 80 + (COLSH) * 2))
#define SB_ADDR(BUF, ROW, COLSH) \
    (S + (uint32_t)(BUF) * STAGE_B + SB_OFF + (uint32_t)((ROW) * 80 + (COLSH) * 2))

    const int cr = tid >> 2;                      // 0..63
    const int ck = (tid & 3) * 8;                 // k offset in elems
    const size_t aBase0 = (size_t)(row0 + cr) * 768 + ck;
    const size_t aBase1 = (size_t)(row0 + cr + 64) * 768 + ck;
    const size_t bBase  = (size_t)(col0 + cr) * 768 + ck;

    const int aq = lane >> 3, al8 = lane & 7;
    const int a_row = wm * 32 + (aq & 1) * 8 + al8;
    const int a_col = (aq >> 1) * 8;
    const int b_row0 = wn * 32 + (aq >> 1) * 8 + al8;
    const int b_col = (aq & 1) * 8;

    float acc[2][4][4];
#pragma unroll
    for (int i = 0; i < 2; i++)
#pragma unroll
        for (int j = 0; j < 4; j++)
#pragma unroll
            for (int c = 0; c < 4; c++) acc[i][j][c] = 0.0f;

#define PREFETCH(BUF, K0)                                                     \
    do {                                                                      \
        CPA16(SA_ADDR(BUF, cr, ck),      g_Xh + aBase0 + (K0));               \
        CPA16(SA_ADDR(BUF, cr + 64, ck), g_Xh + aBase1 + (K0));               \
        CPA16(SB_ADDR(BUF, cr, ck),      g_Wh + bBase + (K0));                \
        CPA_COMMIT();                                                         \
    } while (0)

    PREFETCH(0, 0);
    PREFETCH(1, 32);
    PREFETCH(2, 64);

    for (int t = 0; t < 24; ++t) {
        const int buf = t & 3;
        CPA_WAIT2();
        __syncthreads();
        if (t + 3 < 24) PREFETCH((t + 3) & 3, (t + 3) * 32);

#pragma unroll
        for (int ksub = 0; ksub < 2; ++ksub) {
            const int kc = ksub * 16;
            uint32_t Af[2][4];
            uint32_t Bf[4][2];
#pragma unroll
            for (int fm = 0; fm < 2; fm++)
                ldsm4(Af[fm][0], Af[fm][1], Af[fm][2], Af[fm][3],
                      SA_ADDR(buf, a_row + fm * 16, kc + a_col));
#pragma unroll
            for (int fp = 0; fp < 2; fp++)
                ldsm4(Bf[fp * 2][0], Bf[fp * 2][1], Bf[fp * 2 + 1][0], Bf[fp * 2 + 1][1],
                      SB_ADDR(buf, b_row0 + fp * 16, kc + b_col));
#pragma unroll
            for (int fm = 0; fm < 2; fm++)
#pragma unroll
                for (int fn = 0; fn < 4; fn++)
                    mma16816(acc[fm][fn], Af[fm], Bf[fn]);
        }
    }

    // Epilogue: acc -> g_A (with bias) / g_Bv
    float* dst = part ? g_Bv : g_A;
    const int r_base = row0 + wm * 32 + (lane >> 2);
    const int c_base = hb + wn * 32 + (lane & 3) * 2;
#pragma unroll
    for (int fm = 0; fm < 2; fm++)
#pragma unroll
        for (int fn = 0; fn < 4; fn++) {
            const int cc = c_base + fn * 8;
            float2 b0 = make_float2(0.f, 0.f);
            if (!part) b0 = *reinterpret_cast<const float2*>(bias + cc);
#pragma unroll
            for (int hr = 0; hr < 2; hr++) {
                const int rr = r_base + fm * 16 + hr * 8;
                float2 v;
                v.x = acc[fm][fn][hr * 2 + 0] + b0.x;
                v.y = acc[fm][fn][hr * 2 + 1] + b0.y;
                *reinterpret_cast<float2*>(dst + (size_t)rr * Hh + cc) = v;
            }
        }
}

// ---------------------------------------------------------------------------
// Fast tanh: tanh(z) = 1 - 2/(exp(2z)+1).
// ---------------------------------------------------------------------------
__device__ __forceinline__ float fast_tanh(float z) {
    const float e = __expf(2.0f * z);
    return 1.0f - __fdividef(2.0f, e + 1.0f);
}

// ---------------------------------------------------------------------------
// Kernel 2: out[b, m(i,j), h] = tanh(A[b,i,h] + Bv[b,j,h]) for j >= i.
// Flattened valid-tile grid: blockIdx.x in [0, 2352) maps to (iy, jx) with
// j0+8 > i0 via closed-form inverse of cum(K) = 96K - K(K-1) (row pairs
// iy = 2K, 2K+1 each have 48-K valid j-tiles starting at jx = K).
// Body identical to the proven floor version (ii-outer, bv cached, __stcs).
// ---------------------------------------------------------------------------
__global__ __launch_bounds__(192) void pairs_kernel(float* __restrict__ out) {
    const int b = blockIdx.y;
    const int v = blockIdx.x;

    // Invert cumulative count: K = floor((97 - sqrt(9409 - 4v)) / 2), corrected.
    int K = (int)((97.0 - sqrt(9409.0 - 4.0 * (double)v)) * 0.5);
    while (96 * (K + 1) - (K + 1) * K <= v) ++K;
    while (96 * K - K * (K - 1) > v) --K;
    const int rem = v - (96 * K - K * (K - 1));
    const int w = 48 - K;
    int iy, jx;
    if (rem < w) { iy = 2 * K;     jx = K + rem; }
    else         { iy = 2 * K + 1; jx = K + rem - w; }
    const int i0 = iy * 4;
    const int j0 = jx * 8;

    const int t = threadIdx.x;
    const int h0 = t * 4;

    float4 a[4];
#pragma unroll
    for (int ii = 0; ii < 4; ii++)
        a[ii] = *reinterpret_cast<const float4*>(g_A + (size_t)(b * Lq + i0 + ii) * Hh + h0);

    float4 bv[8];
#pragma unroll
    for (int jj = 0; jj < 8; jj++)
        bv[jj] = *reinterpret_cast<const float4*>(g_Bv + (size_t)(b * Lq + j0 + jj) * Hh + h0);

#pragma unroll
    for (int ii = 0; ii < 4; ii++) {
        const int i = i0 + ii;
        const int rowbase = i * Lq - (i * (i - 1)) / 2 - i;
        float* obase = out + ((size_t)(b * M_PAIRS + rowbase + j0)) * Hh + h0;
#pragma unroll
        for (int jj = 0; jj < 8; jj++) {
            const int j = j0 + jj;
            if (j >= i) {
                float4 vv;
                vv.x = fast_tanh(a[ii].x + bv[jj].x);
                vv.y = fast_tanh(a[ii].y + bv[jj].y);
                vv.z = fast_tanh(a[ii].z + bv[jj].z);
                vv.w = fast_tanh(a[ii].w + bv[jj].w);
                __stcs(reinterpret_cast<float4*>(obase + (size_t)jj * Hh), vv);
            }
        }
    }
}

// ---------------------------------------------------------------------------
// Launch: seq_hiddens [2,384,768] f32, W [768,1536] f32, b [768] f32.
// Output [2, 73920, 768] f32.
// ---------------------------------------------------------------------------
extern "C" void kernel_launch(void* const* d_in, const int* in_sizes, int n_in,
                              void* d_out, int out_size) {
    const float* seq  = (const float*)d_in[0];
    const float* W    = (const float*)d_in[1];
    const float* bias = (const float*)d_in[2];
    float* out = (float*)d_out;

    cudaFuncSetAttribute(mma_gemm, cudaFuncAttributeMaxDynamicSharedMemorySize, GEMM_SMEM);

    convert_kernel<<<(NXE + NWE) / 2048, 256>>>(seq, W);

    dim3 g1(24, 6);       // (N/64 over 1536, M/128 over 768) = 144 CTAs
    mma_gemm<<<g1, 256, GEMM_SMEM>>>(bias);

    dim3 g2(PAIR_TILES, 2);   // valid pair tiles only
    pairs_kernel<<<g2, 192>>>(out);
}

// round 15
// speedup vs baseline: 1.0281x; 1.0171x over previous
#include <cuda_runtime.h>
#include <cuda_fp16.h>
#include <cstdint>
#include <cmath>

// Problem constants
#define Hh 768
#define Lq 384
#define Bq 2
#define NROWS (Bq * Lq)           // 768 rows of (b, l)
#define M_PAIRS 73920             // 384*385/2
#define NXE (768 * 768)           // X elements
#define NWE (1536 * 768)          // W elements (as 1536 virtual K-major rows)
#define PAIR_TILES 2352           // valid (i0/4, j0/8) tiles per batch

// Scratch
__device__ float g_A[NROWS * Hh];             // X @ W[:, :768]^T + bias
__device__ float g_Bv[NROWS * Hh];            // X @ W[:, 768:]^T
__device__ __align__(16) __half g_Xh[NXE];
__device__ __align__(16) __half g_Wh[NWE];

__device__ __forceinline__ uint32_t smem_u32(const void* p) {
    uint32_t a;
    asm("{ .reg .u64 t; cvta.to.shared.u64 t, %1; cvt.u32.u64 %0, t; }" : "=r"(a) : "l"(p));
    return a;
}

// Pack 4 floats -> 4 fp16 (rn) in a uint2
__device__ __forceinline__ uint2 cvt4h(const float4 v) {
    __half2 p0 = __floats2half2_rn(v.x, v.y);
    __half2 p1 = __floats2half2_rn(v.z, v.w);
    uint2 r;
    r.x = *reinterpret_cast<uint32_t*>(&p0);
    r.y = *reinterpret_cast<uint32_t*>(&p1);
    return r;
}

// ---------------------------------------------------------------------------
// Kernel 0: fp32 -> fp16 convert, 8 elems/thread: 2x LDG.128 -> 1x STG.128.
// W re-packed into 1536 K-major virtual rows: row n = p*768+h holds
// W[h, p*768 + k], k in [0,768).
// ---------------------------------------------------------------------------
__global__ __launch_bounds__(256) void convert_kernel(const float* __restrict__ X,
                                                      const float* __restrict__ W) {
    const int e = (blockIdx.x * 256 + threadIdx.x) * 8;
    float4 v0, v1;
    __half* dst;
    if (e < NXE) {
        v0 = *reinterpret_cast<const float4*>(X + e);
        v1 = *reinterpret_cast<const float4*>(X + e + 4);
        dst = g_Xh + e;
    } else {
        const int e2 = e - NXE;
        const int n = e2 / 768;
        const int k = e2 - n * 768;
        const int p = (n >= 768);
        const int h = n - p * 768;
        const float* src = W + (size_t)h * 1536 + p * 768 + k;
        v0 = *reinterpret_cast<const float4*>(src);
        v1 = *reinterpret_cast<const float4*>(src + 4);
        dst = g_Wh + e2;
    }
    const uint2 a = cvt4h(v0);
    const uint2 b = cvt4h(v1);
    *reinterpret_cast<uint4*>(dst) = make_uint4(a.x, a.y, b.x, b.y);
}

// ---------------------------------------------------------------------------
// Kernel 1: single-pass fp16 mma.sync GEMM (fp32 accumulate), BK=32,
// 4-stage cp.async ring. D[m,n] = sum_k Xh[m,k] * Wh[n,k].
// CTA tile 128x64, 8 warps (4m x 2n). 61440 B dynamic smem. 144 CTAs.
// ---------------------------------------------------------------------------
__device__ __forceinline__ void ldsm4(uint32_t& r0, uint32_t& r1, uint32_t& r2,
                                      uint32_t& r3, uint32_t addr) {
    asm volatile("ldmatrix.sync.aligned.m8n8.x4.shared.b16 {%0,%1,%2,%3}, [%4];"
                 : "=r"(r0), "=r"(r1), "=r"(r2), "=r"(r3) : "r"(addr));
}
__device__ __forceinline__ void mma16816(float* d, const uint32_t* a, const uint32_t* b) {
    asm volatile(
        "mma.sync.aligned.m16n8k16.row.col.f32.f16.f16.f32 "
        "{%0,%1,%2,%3}, {%4,%5,%6,%7}, {%8,%9}, {%0,%1,%2,%3};"
        : "+f"(d[0]), "+f"(d[1]), "+f"(d[2]), "+f"(d[3])
        : "r"(a[0]), "r"(a[1]), "r"(a[2]), "r"(a[3]), "r"(b[0]), "r"(b[1]));
}
#define CPA16(dst, src) \
    asm volatile("cp.async.cg.shared.global [%0], [%1], 16;" :: "r"(dst), "l"(src))
#define CPA_COMMIT() asm volatile("cp.async.commit_group;" ::: "memory")
#define CPA_WAIT2()  asm volatile("cp.async.wait_group 2;" ::: "memory")

#define STAGE_B   15360                   // bytes per pipeline stage
#define SB_OFF    10240                   // B tile offset within a stage
#define GEMM_SMEM (4 * STAGE_B)           // 61440

__global__ __launch_bounds__(256) void mma_gemm(const float* __restrict__ bias) {
    extern __shared__ char smem[];
    const uint32_t S = smem_u32(smem);

    const int tid = threadIdx.x;
    const int wid = tid >> 5, lane = tid & 31;
    const int wm = wid >> 1, wn = wid & 1;        // warp grid 4(m) x 2(n)
    const int col0 = blockIdx.x * 64;             // virtual-W-row tile (0..1535)
    const int row0 = blockIdx.y * 128;            // X-row tile (0..767)
    const int part = (col0 >= Hh);
    const int hb = col0 - part * Hh;

#define SA_ADDR(BUF, ROW, COLSH) \
    (S + (uint32_t)(BUF) * STAGE_B + (uint32_t)((ROW) * 80 + (COLSH) * 2))
#define SB_ADDR(BUF, ROW, COLSH) \
    (S + (uint32_t)(BUF) * STAGE_B + SB_OFF + (uint32_t)((ROW) * 80 + (COLSH) * 2))

    const int cr = tid >> 2;                      // 0..63
    const int ck = (tid & 3) * 8;                 // k offset in elems
    const size_t aBase0 = (size_t)(row0 + cr) * 768 + ck;
    const size_t aBase1 = (size_t)(row0 + cr + 64) * 768 + ck;
    const size_t bBase  = (size_t)(col0 + cr) * 768 + ck;

    const int aq = lane >> 3, al8 = lane & 7;
    const int a_row = wm * 32 + (aq & 1) * 8 + al8;
    const int a_col = (aq >> 1) * 8;
    const int b_row0 = wn * 32 + (aq >> 1) * 8 + al8;
    const int b_col = (aq & 1) * 8;

    float acc[2][4][4];
#pragma unroll
    for (int i = 0; i < 2; i++)
#pragma unroll
        for (int j = 0; j < 4; j++)
#pragma unroll
            for (int c = 0; c < 4; c++) acc[i][j][c] = 0.0f;

#define PREFETCH(BUF, K0)                                                     \
    do {                                                                      \
        CPA16(SA_ADDR(BUF, cr, ck),      g_Xh + aBase0 + (K0));               \
        CPA16(SA_ADDR(BUF, cr + 64, ck), g_Xh + aBase1 + (K0));               \
        CPA16(SB_ADDR(BUF, cr, ck),      g_Wh + bBase + (K0));                \
        CPA_COMMIT();                                                         \
    } while (0)

    PREFETCH(0, 0);
    PREFETCH(1, 32);
    PREFETCH(2, 64);

    for (int t = 0; t < 24; ++t) {
        const int buf = t & 3;
        CPA_WAIT2();
        __syncthreads();
        if (t + 3 < 24) PREFETCH((t + 3) & 3, (t + 3) * 32);

#pragma unroll
        for (int ksub = 0; ksub < 2; ++ksub) {
            const int kc = ksub * 16;
            uint32_t Af[2][4];
            uint32_t Bf[4][2];
#pragma unroll
            for (int fm = 0; fm < 2; fm++)
                ldsm4(Af[fm][0], Af[fm][1], Af[fm][2], Af[fm][3],
                      SA_ADDR(buf, a_row + fm * 16, kc + a_col));
#pragma unroll
            for (int fp = 0; fp < 2; fp++)
                ldsm4(Bf[fp * 2][0], Bf[fp * 2][1], Bf[fp * 2 + 1][0], Bf[fp * 2 + 1][1],
                      SB_ADDR(buf, b_row0 + fp * 16, kc + b_col));
#pragma unroll
            for (int fm = 0; fm < 2; fm++)
#pragma unroll
                for (int fn = 0; fn < 4; fn++)
                    mma16816(acc[fm][fn], Af[fm], Bf[fn]);
        }
    }

    // Epilogue: acc -> g_A (with bias) / g_Bv
    float* dst = part ? g_Bv : g_A;
    const int r_base = row0 + wm * 32 + (lane >> 2);
    const int c_base = hb + wn * 32 + (lane & 3) * 2;
#pragma unroll
    for (int fm = 0; fm < 2; fm++)
#pragma unroll
        for (int fn = 0; fn < 4; fn++) {
            const int cc = c_base + fn * 8;
            float2 b0 = make_float2(0.f, 0.f);
            if (!part) b0 = *reinterpret_cast<const float2*>(bias + cc);
#pragma unroll
            for (int hr = 0; hr < 2; hr++) {
                const int rr = r_base + fm * 16 + hr * 8;
                float2 v;
                v.x = acc[fm][fn][hr * 2 + 0] + b0.x;
                v.y = acc[fm][fn][hr * 2 + 1] + b0.y;
                *reinterpret_cast<float2*>(dst + (size_t)rr * Hh + cc) = v;
            }
        }
}

// ---------------------------------------------------------------------------
// tanh via single MUFU.TANH (sm_75+ tanh.approx.f32, ~4.9e-4 max abs err).
// ---------------------------------------------------------------------------
__device__ __forceinline__ float fast_tanh(float z) {
    float r;
    asm("tanh.approx.f32 %0, %1;" : "=f"(r) : "f"(z));
    return r;
}

// ---------------------------------------------------------------------------
// Kernel 2: out[b, m(i,j), h] = tanh(A[b,i,h] + Bv[b,j,h]) for j >= i.
// Flattened valid-tile grid (2352 blocks/batch, zero dead blocks), ii-outer,
// bv cached, __stcs streaming stores.
// ---------------------------------------------------------------------------
__global__ __launch_bounds__(192) void pairs_kernel(float* __restrict__ out) {
    const int b = blockIdx.y;
    const int v = blockIdx.x;

    // Invert cumulative count: K = floor((97 - sqrt(9409 - 4v)) / 2), corrected.
    int K = (int)((97.0 - sqrt(9409.0 - 4.0 * (double)v)) * 0.5);
    while (96 * (K + 1) - (K + 1) * K <= v) ++K;
    while (96 * K - K * (K - 1) > v) --K;
    const int rem = v - (96 * K - K * (K - 1));
    const int w = 48 - K;
    int iy, jx;
    if (rem < w) { iy = 2 * K;     jx = K + rem; }
    else         { iy = 2 * K + 1; jx = K + rem - w; }
    const int i0 = iy * 4;
    const int j0 = jx * 8;

    const int t = threadIdx.x;
    const int h0 = t * 4;

    float4 a[4];
#pragma unroll
    for (int ii = 0; ii < 4; ii++)
        a[ii] = *reinterpret_cast<const float4*>(g_A + (size_t)(b * Lq + i0 + ii) * Hh + h0);

    float4 bv[8];
#pragma unroll
    for (int jj = 0; jj < 8; jj++)
        bv[jj] = *reinterpret_cast<const float4*>(g_Bv + (size_t)(b * Lq + j0 + jj) * Hh + h0);

#pragma unroll
    for (int ii = 0; ii < 4; ii++) {
        const int i = i0 + ii;
        const int rowbase = i * Lq - (i * (i - 1)) / 2 - i;
        float* obase = out + ((size_t)(b * M_PAIRS + rowbase + j0)) * Hh + h0;
#pragma unroll
        for (int jj = 0; jj < 8; jj++) {
            const int j = j0 + jj;
            if (j >= i) {
                float4 vv;
                vv.x = fast_tanh(a[ii].x + bv[jj].x);
                vv.y = fast_tanh(a[ii].y + bv[jj].y);
                vv.z = fast_tanh(a[ii].z + bv[jj].z);
                vv.w = fast_tanh(a[ii].w + bv[jj].w);
                __stcs(reinterpret_cast<float4*>(obase + (size_t)jj * Hh), vv);
            }
        }
    }
}

// ---------------------------------------------------------------------------
// Launch: seq_hiddens [2,384,768] f32, W [768,1536] f32, b [768] f32.
// Output [2, 73920, 768] f32.
// ---------------------------------------------------------------------------
extern "C" void kernel_launch(void* const* d_in, const int* in_sizes, int n_in,
                              void* d_out, int out_size) {
    const float* seq  = (const float*)d_in[0];
    const float* W    = (const float*)d_in[1];
    const float* bias = (const float*)d_in[2];
    float* out = (float*)d_out;

    cudaFuncSetAttribute(mma_gemm, cudaFuncAttributeMaxDynamicSharedMemorySize, GEMM_SMEM);

    convert_kernel<<<(NXE + NWE) / 2048, 256>>>(seq, W);

    dim3 g1(24, 6);       // (N/64 over 1536, M/128 over 768) = 144 CTAs
    mma_gemm<<<g1, 256, GEMM_SMEM>>>(bias);

    dim3 g2(PAIR_TILES, 2);   // valid pair tiles only
    pairs_kernel<<<g2, 192>>>(out);
}